// round 5
// baseline (speedup 1.0000x reference)
#include <cuda_runtime.h>
#include <math.h>

#define N_PTS 30000
#define M_AT  8000
#define D     16
#define KNN   16
#define NK    (N_PTS*KNN)
#define BN_EPS 1e-5
#define SLOPE 0.2f
#define TSPLIT 4
#define PERCH  (M_AT/TSPLIT)   // 2000 atoms per chunk-thread

// ---- scratch (device globals) ----
__device__ float4 g_atoms[M_AT];          // x,y,z,|y|^2
__device__ float4 g_t4[M_AT*4];           // transformed atom feats (16 f = 4 quads)
__device__ int    g_idx[NK];
__device__ float  g_invd[NK];
__device__ float4 g_h1v[NK*4];            // leaky(conv1) pre-BN
__device__ float4 g_h2v[NK*4];            // leaky(conv2) pre-BN
__device__ float  g_fx1[N_PTS*D];
__device__ double g_stats[4*D];
__device__ float4 g_A1v[4], g_B1v[4], g_A2v[4], g_B2v[4];

__device__ __forceinline__ float lrelu(float x){ return x > 0.f ? x : SLOPE*x; }

__global__ void k_init(){
  int i = threadIdx.x;
  if (i < 4*D) g_stats[i] = 0.0;
}

// ---- transform_types MLP + atom packing ----
__global__ void __launch_bounds__(256) k_prep(
    const float* __restrict__ atom_types, const float* __restrict__ atom_xyz,
    const float* __restrict__ Wt1, const float* __restrict__ bt1,
    const float* __restrict__ Wt2, const float* __restrict__ bt2,
    const float* __restrict__ Wt3, const float* __restrict__ bt3){
  __shared__ float sW[3][D][D];
  __shared__ float sb[3][D];
  __shared__ float s_row[D][D+1];
  int tid = threadIdx.x;
  sW[0][tid>>4][tid&15] = Wt1[tid];
  sW[1][tid>>4][tid&15] = Wt2[tid];
  sW[2][tid>>4][tid&15] = Wt3[tid];
  if (tid < D){ sb[0][tid]=bt1[tid]; sb[1][tid]=bt2[tid]; sb[2][tid]=bt3[tid]; }
  __syncthreads();
  int r = tid>>4, d = tid&15;
  int atom = blockIdx.x*16 + r;
  float v = atom_types[atom*D+d];
  #pragma unroll
  for (int L=0; L<3; L++){
    s_row[r][d] = v;
    __syncthreads();
    float acc = sb[L][d];
    #pragma unroll
    for (int i=0;i<D;i++) acc = fmaf(s_row[r][i], sW[L][i][d], acc);
    v = lrelu(acc);
    __syncthreads();
  }
  ((float*)g_t4)[atom*D+d] = v;
  if (d == 0){
    float x = atom_xyz[atom*3+0], y = atom_xyz[atom*3+1], z = atom_xyz[atom*3+2];
    g_atoms[atom] = make_float4(x, y, z, x*x + y*y + z*z);
  }
}

// ---- kNN: 4 threads per point, each scans a contiguous 2000-atom chunk ----
__global__ void __launch_bounds__(256) k_knn(const float* __restrict__ xyz){
  __shared__ float sv[64][TSPLIT][KNN];
  __shared__ int   si[64][TSPLIT][KNN];
  int grp = threadIdx.x >> 2;              // 0..63 point groups in block
  int c   = threadIdx.x & 3;               // chunk id
  int pt  = blockIdx.x*64 + grp;
  bool act = pt < N_PTS;
  float px=0.f, py=0.f, pz=0.f;
  if (act){ px = xyz[pt*3+0]; py = xyz[pt*3+1]; pz = xyz[pt*3+2]; }
  float qx = -2.f*px, qy = -2.f*py, qz = -2.f*pz;

  float bd[KNN]; int bi[KNN];
  #pragma unroll
  for (int j=0;j<KNN;j++){ bd[j] = 3.4e38f; bi[j] = 0; }

  if (act){
    int base = c*PERCH;
    #pragma unroll 4
    for (int i=0;i<PERCH;i++){
      float4 a = __ldg(&g_atoms[base+i]);
      float v = fmaf(qx, a.x, a.w);
      v = fmaf(qy, a.y, v);
      v = fmaf(qz, a.z, v);            // v = |a|^2 - 2 p.a  (= d2 - |p|^2)
      if (v < bd[KNN-1]){
        bd[KNN-1] = v; bi[KNN-1] = base + i;
        #pragma unroll
        for (int j=KNN-1; j>0; j--){
          if (bd[j] < bd[j-1]){
            float td=bd[j]; bd[j]=bd[j-1]; bd[j-1]=td;
            int   ti=bi[j]; bi[j]=bi[j-1]; bi[j-1]=ti;
          } else break;
        }
      }
    }
  }
  #pragma unroll
  for (int j=0;j<KNN;j++){ sv[grp][c][j]=bd[j]; si[grp][c][j]=bi[j]; }
  __syncwarp();
  if (c == 0 && act){
    int h0=0,h1=0,h2=0,h3=0;
    #pragma unroll
    for (int r=0;r<KNN;r++){
      float v0=sv[grp][0][h0], v1=sv[grp][1][h1], v2=sv[grp][2][h2], v3=sv[grp][3][h3];
      // strict < : lowest chunk (= lowest index range) wins ties
      int bc = 0; float bv = v0;
      if (v1 < bv){ bv=v1; bc=1; }
      if (v2 < bv){ bv=v2; bc=2; }
      if (v3 < bv){ bv=v3; bc=3; }
      int a;
      if      (bc==0){ a=si[grp][0][h0]; h0++; }
      else if (bc==1){ a=si[grp][1][h1]; h1++; }
      else if (bc==2){ a=si[grp][2][h2]; h2++; }
      else           { a=si[grp][3][h3]; h3++; }
      float4 av = g_atoms[a];
      float dx = px-av.x, dy = py-av.y, dz = pz-av.z;
      float dist = dx*dx + dy*dy + dz*dz;
      g_idx [pt*KNN+r] = a;
      g_invd[pt*KNN+r] = 1.0f/dist;
    }
  }
}

// ---- conv1 + leaky + bn1 stats (8 points per block-iteration) ----
__global__ void __launch_bounds__(256) k_conv1(const float* __restrict__ W1,
                                               const float* __restrict__ b1){
  __shared__ float s_f[128][20];     // 8 pts x 16 k rows, 17 feats (padded 20)
  __shared__ float s_red[16][17];
  int tid = threadIdx.x;
  // per-thread W column in registers
  int d = tid & 15;
  float Wc[D+1];
  #pragma unroll
  for (int i=0;i<=D;i++) Wc[i] = W1[i*D + d];
  float bb = b1[d];
  int rA = tid >> 1, hA = tid & 1;   // phase-A row/half
  int gB = tid >> 4;                 // phase-B row group (8 rows each)
  float lsum = 0.f, lsq = 0.f;

  for (int grp = blockIdx.x; grp < N_PTS/8; grp += gridDim.x){
    int base = grp*8*KNN;            // first row (point*K) of this group
    // Phase A: gather features
    {
      int rowg = base + rA;
      int a = g_idx[rowg];
      float4 v0 = g_t4[a*4 + hA*2 + 0];
      float4 v1 = g_t4[a*4 + hA*2 + 1];
      *(float4*)&s_f[rA][hA*8 + 0] = v0;
      *(float4*)&s_f[rA][hA*8 + 4] = v1;
      if (hA == 0) s_f[rA][16] = g_invd[rowg];
    }
    __syncthreads();
    // Phase B: 8 rows per thread
    #pragma unroll
    for (int s=0;s<8;s++){
      int r = gB*8 + s;
      float acc = bb;
      #pragma unroll
      for (int q=0;q<4;q++){
        float4 f = *(const float4*)&s_f[r][q*4];
        acc = fmaf(f.x, Wc[q*4+0], acc);
        acc = fmaf(f.y, Wc[q*4+1], acc);
        acc = fmaf(f.z, Wc[q*4+2], acc);
        acc = fmaf(f.w, Wc[q*4+3], acc);
      }
      acc = fmaf(s_f[r][16], Wc[16], acc);
      float h = lrelu(acc);
      ((float*)g_h1v)[(base + r)*D + d] = h;
      lsum += h; lsq = fmaf(h, h, lsq);
    }
    __syncthreads();
  }
  // stats reduction
  s_red[gB][d] = lsum;
  __syncthreads();
  if (tid < D){
    float s = 0.f;
    #pragma unroll
    for (int j=0;j<16;j++) s += s_red[j][tid];
    atomicAdd(&g_stats[tid], (double)s);
  }
  __syncthreads();
  s_red[gB][d] = lsq;
  __syncthreads();
  if (tid < D){
    float s = 0.f;
    #pragma unroll
    for (int j=0;j<16;j++) s += s_red[j][tid];
    atomicAdd(&g_stats[D+tid], (double)s);
  }
}

// ---- BN finalize: fold into affine A*x+B ----
__global__ void k_fin(const float* __restrict__ gma, const float* __restrict__ bet,
                      int stage){
  int d = threadIdx.x;
  if (d >= D) return;
  double s  = g_stats[stage*2*D + d];
  double sq = g_stats[stage*2*D + D + d];
  double mean = s / (double)NK;
  double var  = sq / (double)NK - mean*mean;
  float inv = (float)(1.0 / sqrt(var + BN_EPS));
  float Av = inv * gma[d];
  float Bv = bet[d] - (float)mean * Av;
  if (stage == 0){ ((float*)g_A1v)[d]=Av; ((float*)g_B1v)[d]=Bv; }
  else           { ((float*)g_A2v)[d]=Av; ((float*)g_B2v)[d]=Bv; }
}

// ---- bn1 apply + K-sum pool + conv2 + leaky + bn2 stats ----
__global__ void __launch_bounds__(256) k_stage2(const float* __restrict__ W2,
                                                const float* __restrict__ b2){
  __shared__ float s_f[128][20];
  __shared__ float s_red[16][17];
  int tid = threadIdx.x;
  int d = tid & 15;
  float Wc[D];
  #pragma unroll
  for (int i=0;i<D;i++) Wc[i] = W2[i*D + d];
  float bb = b2[d];
  int rA = tid >> 1, hA = tid & 1;
  float4 Aq0 = g_A1v[hA*2], Aq1 = g_A1v[hA*2+1];
  float4 Bq0 = g_B1v[hA*2], Bq1 = g_B1v[hA*2+1];
  int gB = tid >> 4;
  int pP = tid >> 4, dP = tid & 15;  // pooling assignment (tid<128): point pP in 0..7
  float lsum = 0.f, lsq = 0.f;

  for (int grp = blockIdx.x; grp < N_PTS/8; grp += gridDim.x){
    int base = grp*8*KNN;
    // Phase A: load h1, apply BN1 affine
    {
      int rowg = base + rA;
      float4 v0 = g_h1v[rowg*4 + hA*2 + 0];
      float4 v1 = g_h1v[rowg*4 + hA*2 + 1];
      float4 f0, f1;
      f0.x = fmaf(v0.x, Aq0.x, Bq0.x); f0.y = fmaf(v0.y, Aq0.y, Bq0.y);
      f0.z = fmaf(v0.z, Aq0.z, Bq0.z); f0.w = fmaf(v0.w, Aq0.w, Bq0.w);
      f1.x = fmaf(v1.x, Aq1.x, Bq1.x); f1.y = fmaf(v1.y, Aq1.y, Bq1.y);
      f1.z = fmaf(v1.z, Aq1.z, Bq1.z); f1.w = fmaf(v1.w, Aq1.w, Bq1.w);
      *(float4*)&s_f[rA][hA*8 + 0] = f0;
      *(float4*)&s_f[rA][hA*8 + 4] = f1;
    }
    __syncthreads();
    // Phase B: conv2 on each row + (tid<128) pooled fx1
    #pragma unroll
    for (int s=0;s<8;s++){
      int r = gB*8 + s;
      float acc = bb;
      #pragma unroll
      for (int q=0;q<4;q++){
        float4 f = *(const float4*)&s_f[r][q*4];
        acc = fmaf(f.x, Wc[q*4+0], acc);
        acc = fmaf(f.y, Wc[q*4+1], acc);
        acc = fmaf(f.z, Wc[q*4+2], acc);
        acc = fmaf(f.w, Wc[q*4+3], acc);
      }
      float h = lrelu(acc);
      ((float*)g_h2v)[(base + r)*D + d] = h;
      lsum += h; lsq = fmaf(h, h, lsq);
    }
    if (tid < 128){
      float s = 0.f;
      #pragma unroll
      for (int k=0;k<KNN;k++) s += s_f[pP*16 + k][dP];
      g_fx1[(grp*8 + pP)*D + dP] = s;
    }
    __syncthreads();
  }
  s_red[gB][d] = lsum;
  __syncthreads();
  if (tid < D){
    float s = 0.f;
    #pragma unroll
    for (int j=0;j<16;j++) s += s_red[j][tid];
    atomicAdd(&g_stats[2*D+tid], (double)s);
  }
  __syncthreads();
  s_red[gB][d] = lsq;
  __syncthreads();
  if (tid < D){
    float s = 0.f;
    #pragma unroll
    for (int j=0;j<16;j++) s += s_red[j][tid];
    atomicAdd(&g_stats[3*D+tid], (double)s);
  }
}

// ---- bn2 apply + K-sum + concat + final Linear(32,16): 16 points/iter ----
__global__ void __launch_bounds__(256) k_stage3(const float* __restrict__ W3,
                                                const float* __restrict__ b3,
                                                float* __restrict__ out){
  __shared__ float sW[2*D][D];
  __shared__ float s1[16][17];
  __shared__ float s2[16][17];
  int tid = threadIdx.x;
  for (int i=tid; i<2*D*D; i+=256) sW[i>>4][i&15] = W3[i];
  int p = tid >> 4, d = tid & 15;
  float a2 = ((const float*)g_A2v)[d];
  float b2k = 16.f * ((const float*)g_B2v)[d];
  float bb = b3[d];
  __syncthreads();

  for (int grp = blockIdx.x; grp < N_PTS/16; grp += gridDim.x){
    int P0 = grp*16;
    s1[p][d] = g_fx1[(P0+p)*D + d];
    float s = 0.f;
    const float* h2 = (const float*)g_h2v;
    #pragma unroll
    for (int k=0;k<KNN;k++) s += h2[((P0+p)*KNN + k)*D + d];
    s2[p][d] = fmaf(a2, s, b2k);
    __syncthreads();
    float acc = bb;
    #pragma unroll
    for (int i=0;i<D;i++) acc = fmaf(s1[p][i], sW[i][d], acc);
    #pragma unroll
    for (int i=0;i<D;i++) acc = fmaf(s2[p][i], sW[D+i][d], acc);
    out[(P0+p)*D + d] = acc;
    __syncthreads();
  }
}

extern "C" void kernel_launch(void* const* d_in, const int* in_sizes, int n_in,
                              void* d_out, int out_size){
  const float* xyz        = (const float*)d_in[0];
  const float* atom_xyz   = (const float*)d_in[1];
  const float* atom_types = (const float*)d_in[2];
  const float* Wt1 = (const float*)d_in[3];  const float* bt1 = (const float*)d_in[4];
  const float* Wt2 = (const float*)d_in[5];  const float* bt2 = (const float*)d_in[6];
  const float* Wt3 = (const float*)d_in[7];  const float* bt3 = (const float*)d_in[8];
  const float* W1  = (const float*)d_in[9];  const float* b1  = (const float*)d_in[10];
  const float* W2  = (const float*)d_in[11]; const float* b2  = (const float*)d_in[12];
  const float* W3  = (const float*)d_in[13]; const float* b3  = (const float*)d_in[14];
  const float* g1  = (const float*)d_in[15]; const float* be1 = (const float*)d_in[16];
  const float* g2  = (const float*)d_in[17]; const float* be2 = (const float*)d_in[18];
  float* out = (float*)d_out;

  k_init  <<<1, 64>>>();
  k_prep  <<<M_AT/16, 256>>>(atom_types, atom_xyz, Wt1,bt1, Wt2,bt2, Wt3,bt3);
  k_knn   <<<(N_PTS+63)/64, 256>>>(xyz);
  k_conv1 <<<592, 256>>>(W1, b1);
  k_fin   <<<1, 16>>>(g1, be1, 0);
  k_stage2<<<592, 256>>>(W2, b2);
  k_fin   <<<1, 16>>>(g2, be2, 1);
  k_stage3<<<592, 256>>>(W3, b3, out);
}

// round 7
// speedup vs baseline: 3.1036x; 3.1036x over previous
#include <cuda_runtime.h>
#include <math.h>

#define N_PTS 30000
#define M_AT  8000
#define D     16
#define KNN   16
#define NK    (N_PTS*KNN)
#define BN_EPS 1e-5
#define SLOPE 0.2f
#define TSPLIT 2
#define PERCH  (M_AT/TSPLIT)   // 4000 atoms per chunk-thread

// ---- scratch (device globals) ----
__device__ float4 g_atoms[M_AT];          // x,y,z,|y|^2
__device__ float4 g_t4[M_AT*4];           // transformed atom feats (16 f = 4 quads)
__device__ int    g_idx[NK];
__device__ float  g_invd[NK];
__device__ float4 g_h1v[NK*4];            // leaky(conv1) pre-BN
__device__ float4 g_h2v[NK*4];            // leaky(conv2) pre-BN
__device__ float  g_fx1[N_PTS*D];
__device__ double g_stats[4*D];
__device__ float4 g_A1v[4], g_B1v[4], g_A2v[4], g_B2v[4];

__device__ __forceinline__ float lrelu(float x){ return x > 0.f ? x : SLOPE*x; }

__global__ void k_init(){
  int i = threadIdx.x;
  if (i < 4*D) g_stats[i] = 0.0;
}

// ---- transform_types MLP + atom packing ----
__global__ void __launch_bounds__(256) k_prep(
    const float* __restrict__ atom_types, const float* __restrict__ atom_xyz,
    const float* __restrict__ Wt1, const float* __restrict__ bt1,
    const float* __restrict__ Wt2, const float* __restrict__ bt2,
    const float* __restrict__ Wt3, const float* __restrict__ bt3){
  __shared__ float sW[3][D][D];
  __shared__ float sb[3][D];
  __shared__ float s_row[D][D+1];
  int tid = threadIdx.x;
  sW[0][tid>>4][tid&15] = Wt1[tid];
  sW[1][tid>>4][tid&15] = Wt2[tid];
  sW[2][tid>>4][tid&15] = Wt3[tid];
  if (tid < D){ sb[0][tid]=bt1[tid]; sb[1][tid]=bt2[tid]; sb[2][tid]=bt3[tid]; }
  __syncthreads();
  int r = tid>>4, d = tid&15;
  int atom = blockIdx.x*16 + r;
  float v = atom_types[atom*D+d];
  #pragma unroll
  for (int L=0; L<3; L++){
    s_row[r][d] = v;
    __syncthreads();
    float acc = sb[L][d];
    #pragma unroll
    for (int i=0;i<D;i++) acc = fmaf(s_row[r][i], sW[L][i][d], acc);
    v = lrelu(acc);
    __syncthreads();
  }
  ((float*)g_t4)[atom*D+d] = v;
  if (d == 0){
    float x = atom_xyz[atom*3+0], y = atom_xyz[atom*3+1], z = atom_xyz[atom*3+2];
    g_atoms[atom] = make_float4(x, y, z, x*x + y*y + z*z);
  }
}

// ---- kNN: 2 threads per point, each scans a contiguous 4000-atom chunk ----
__global__ void __launch_bounds__(256) k_knn(const float* __restrict__ xyz){
  __shared__ float sv[128][TSPLIT][KNN];
  __shared__ int   si[128][TSPLIT][KNN];
  int grp = threadIdx.x >> 1;              // 0..127 point slots in block
  int c   = threadIdx.x & 1;               // chunk id
  int pt  = blockIdx.x*128 + grp;
  bool act = pt < N_PTS;
  float px=0.f, py=0.f, pz=0.f;
  if (act){ px = xyz[pt*3+0]; py = xyz[pt*3+1]; pz = xyz[pt*3+2]; }
  float qx = -2.f*px, qy = -2.f*py, qz = -2.f*pz;

  float bd[KNN]; int bi[KNN];
  #pragma unroll
  for (int j=0;j<KNN;j++){ bd[j] = 3.4e38f; bi[j] = 0; }

  if (act){
    int base = c*PERCH;
    #pragma unroll 4
    for (int i=0;i<PERCH;i++){
      float4 a = __ldg(&g_atoms[base+i]);
      float v = fmaf(qx, a.x, a.w);
      v = fmaf(qy, a.y, v);
      v = fmaf(qz, a.z, v);            // v = |a|^2 - 2 p.a  (= d2 - |p|^2)
      if (v < bd[KNN-1]){              // strict <: matches jax lower-index ties
        bd[KNN-1] = v; bi[KNN-1] = base + i;
        #pragma unroll
        for (int j=KNN-1; j>0; j--){   // straight chain, NO break: stays in regs
          bool sw = bd[j] < bd[j-1];
          float tv = sw ? bd[j-1] : bd[j];
          bd[j-1]  = sw ? bd[j] : bd[j-1];
          bd[j]    = tv;
          int ti   = sw ? bi[j-1] : bi[j];
          bi[j-1]  = sw ? bi[j] : bi[j-1];
          bi[j]    = ti;
        }
      }
    }
  }
  #pragma unroll
  for (int j=0;j<KNN;j++){ sv[grp][c][j]=bd[j]; si[grp][c][j]=bi[j]; }
  __syncwarp();
  if (c == 0 && act){
    int h0=0, h1=0;
    #pragma unroll
    for (int r=0;r<KNN;r++){
      float v0=sv[grp][0][h0], v1=sv[grp][1][h1];
      int a;
      if (v1 < v0){ a = si[grp][1][h1]; h1++; }   // tie -> chunk 0 (lower indices)
      else        { a = si[grp][0][h0]; h0++; }
      float4 av = g_atoms[a];
      float dx = px-av.x, dy = py-av.y, dz = pz-av.z;
      float dist = dx*dx + dy*dy + dz*dz;         // exact recompute (as in reference)
      g_idx [pt*KNN+r] = a;
      g_invd[pt*KNN+r] = 1.0f/dist;
    }
  }
}

// ---- conv1 + leaky + bn1 stats (8 points per block-iteration) ----
__global__ void __launch_bounds__(256) k_conv1(const float* __restrict__ W1,
                                               const float* __restrict__ b1){
  __shared__ float s_f[128][20];     // 8 pts x 16 k rows, 17 feats (padded 20)
  __shared__ float s_red[16][17];
  int tid = threadIdx.x;
  int d = tid & 15;
  float Wc[D+1];
  #pragma unroll
  for (int i=0;i<=D;i++) Wc[i] = W1[i*D + d];
  float bb = b1[d];
  int rA = tid >> 1, hA = tid & 1;   // phase-A row/half
  int gB = tid >> 4;                 // phase-B row group (8 rows each)
  float lsum = 0.f, lsq = 0.f;

  for (int grp = blockIdx.x; grp < N_PTS/8; grp += gridDim.x){
    int base = grp*8*KNN;
    {
      int rowg = base + rA;
      int a = g_idx[rowg];
      float4 v0 = g_t4[a*4 + hA*2 + 0];
      float4 v1 = g_t4[a*4 + hA*2 + 1];
      *(float4*)&s_f[rA][hA*8 + 0] = v0;
      *(float4*)&s_f[rA][hA*8 + 4] = v1;
      if (hA == 0) s_f[rA][16] = g_invd[rowg];
    }
    __syncthreads();
    #pragma unroll
    for (int s=0;s<8;s++){
      int r = gB*8 + s;
      float acc = bb;
      #pragma unroll
      for (int q=0;q<4;q++){
        float4 f = *(const float4*)&s_f[r][q*4];
        acc = fmaf(f.x, Wc[q*4+0], acc);
        acc = fmaf(f.y, Wc[q*4+1], acc);
        acc = fmaf(f.z, Wc[q*4+2], acc);
        acc = fmaf(f.w, Wc[q*4+3], acc);
      }
      acc = fmaf(s_f[r][16], Wc[16], acc);
      float h = lrelu(acc);
      ((float*)g_h1v)[(base + r)*D + d] = h;
      lsum += h; lsq = fmaf(h, h, lsq);
    }
    __syncthreads();
  }
  s_red[gB][d] = lsum;
  __syncthreads();
  if (tid < D){
    float s = 0.f;
    #pragma unroll
    for (int j=0;j<16;j++) s += s_red[j][tid];
    atomicAdd(&g_stats[tid], (double)s);
  }
  __syncthreads();
  s_red[gB][d] = lsq;
  __syncthreads();
  if (tid < D){
    float s = 0.f;
    #pragma unroll
    for (int j=0;j<16;j++) s += s_red[j][tid];
    atomicAdd(&g_stats[D+tid], (double)s);
  }
}

// ---- BN finalize: fold into affine A*x+B ----
__global__ void k_fin(const float* __restrict__ gma, const float* __restrict__ bet,
                      int stage){
  int d = threadIdx.x;
  if (d >= D) return;
  double s  = g_stats[stage*2*D + d];
  double sq = g_stats[stage*2*D + D + d];
  double mean = s / (double)NK;
  double var  = sq / (double)NK - mean*mean;
  float inv = (float)(1.0 / sqrt(var + BN_EPS));
  float Av = inv * gma[d];
  float Bv = bet[d] - (float)mean * Av;
  if (stage == 0){ ((float*)g_A1v)[d]=Av; ((float*)g_B1v)[d]=Bv; }
  else           { ((float*)g_A2v)[d]=Av; ((float*)g_B2v)[d]=Bv; }
}

// ---- bn1 apply + K-sum pool + conv2 + leaky + bn2 stats ----
__global__ void __launch_bounds__(256) k_stage2(const float* __restrict__ W2,
                                                const float* __restrict__ b2){
  __shared__ float s_f[128][20];
  __shared__ float s_red[16][17];
  int tid = threadIdx.x;
  int d = tid & 15;
  float Wc[D];
  #pragma unroll
  for (int i=0;i<D;i++) Wc[i] = W2[i*D + d];
  float bb = b2[d];
  int rA = tid >> 1, hA = tid & 1;
  float4 Aq0 = g_A1v[hA*2], Aq1 = g_A1v[hA*2+1];
  float4 Bq0 = g_B1v[hA*2], Bq1 = g_B1v[hA*2+1];
  int gB = tid >> 4;
  int pP = tid >> 4, dP = tid & 15;
  float lsum = 0.f, lsq = 0.f;

  for (int grp = blockIdx.x; grp < N_PTS/8; grp += gridDim.x){
    int base = grp*8*KNN;
    {
      int rowg = base + rA;
      float4 v0 = g_h1v[rowg*4 + hA*2 + 0];
      float4 v1 = g_h1v[rowg*4 + hA*2 + 1];
      float4 f0, f1;
      f0.x = fmaf(v0.x, Aq0.x, Bq0.x); f0.y = fmaf(v0.y, Aq0.y, Bq0.y);
      f0.z = fmaf(v0.z, Aq0.z, Bq0.z); f0.w = fmaf(v0.w, Aq0.w, Bq0.w);
      f1.x = fmaf(v1.x, Aq1.x, Bq1.x); f1.y = fmaf(v1.y, Aq1.y, Bq1.y);
      f1.z = fmaf(v1.z, Aq1.z, Bq1.z); f1.w = fmaf(v1.w, Aq1.w, Bq1.w);
      *(float4*)&s_f[rA][hA*8 + 0] = f0;
      *(float4*)&s_f[rA][hA*8 + 4] = f1;
    }
    __syncthreads();
    #pragma unroll
    for (int s=0;s<8;s++){
      int r = gB*8 + s;
      float acc = bb;
      #pragma unroll
      for (int q=0;q<4;q++){
        float4 f = *(const float4*)&s_f[r][q*4];
        acc = fmaf(f.x, Wc[q*4+0], acc);
        acc = fmaf(f.y, Wc[q*4+1], acc);
        acc = fmaf(f.z, Wc[q*4+2], acc);
        acc = fmaf(f.w, Wc[q*4+3], acc);
      }
      float h = lrelu(acc);
      ((float*)g_h2v)[(base + r)*D + d] = h;
      lsum += h; lsq = fmaf(h, h, lsq);
    }
    if (tid < 128){
      float s = 0.f;
      #pragma unroll
      for (int k=0;k<KNN;k++) s += s_f[pP*16 + k][dP];
      g_fx1[(grp*8 + pP)*D + dP] = s;
    }
    __syncthreads();
  }
  s_red[gB][d] = lsum;
  __syncthreads();
  if (tid < D){
    float s = 0.f;
    #pragma unroll
    for (int j=0;j<16;j++) s += s_red[j][tid];
    atomicAdd(&g_stats[2*D+tid], (double)s);
  }
  __syncthreads();
  s_red[gB][d] = lsq;
  __syncthreads();
  if (tid < D){
    float s = 0.f;
    #pragma unroll
    for (int j=0;j<16;j++) s += s_red[j][tid];
    atomicAdd(&g_stats[3*D+tid], (double)s);
  }
}

// ---- bn2 apply + K-sum + concat + final Linear(32,16): 16 points/iter ----
__global__ void __launch_bounds__(256) k_stage3(const float* __restrict__ W3,
                                                const float* __restrict__ b3,
                                                float* __restrict__ out){
  __shared__ float sW[2*D][D];
  __shared__ float s1[16][17];
  __shared__ float s2[16][17];
  int tid = threadIdx.x;
  for (int i=tid; i<2*D*D; i+=256) sW[i>>4][i&15] = W3[i];
  int p = tid >> 4, d = tid & 15;
  float a2 = ((const float*)g_A2v)[d];
  float b2k = 16.f * ((const float*)g_B2v)[d];
  float bb = b3[d];
  __syncthreads();

  for (int grp = blockIdx.x; grp < N_PTS/16; grp += gridDim.x){
    int P0 = grp*16;
    s1[p][d] = g_fx1[(P0+p)*D + d];
    float s = 0.f;
    const float* h2 = (const float*)g_h2v;
    #pragma unroll
    for (int k=0;k<KNN;k++) s += h2[((P0+p)*KNN + k)*D + d];
    s2[p][d] = fmaf(a2, s, b2k);
    __syncthreads();
    float acc = bb;
    #pragma unroll
    for (int i=0;i<D;i++) acc = fmaf(s1[p][i], sW[i][d], acc);
    #pragma unroll
    for (int i=0;i<D;i++) acc = fmaf(s2[p][i], sW[D+i][d], acc);
    out[(P0+p)*D + d] = acc;
    __syncthreads();
  }
}

extern "C" void kernel_launch(void* const* d_in, const int* in_sizes, int n_in,
                              void* d_out, int out_size){
  const float* xyz        = (const float*)d_in[0];
  const float* atom_xyz   = (const float*)d_in[1];
  const float* atom_types = (const float*)d_in[2];
  const float* Wt1 = (const float*)d_in[3];  const float* bt1 = (const float*)d_in[4];
  const float* Wt2 = (const float*)d_in[5];  const float* bt2 = (const float*)d_in[6];
  const float* Wt3 = (const float*)d_in[7];  const float* bt3 = (const float*)d_in[8];
  const float* W1  = (const float*)d_in[9];  const float* b1  = (const float*)d_in[10];
  const float* W2  = (const float*)d_in[11]; const float* b2  = (const float*)d_in[12];
  const float* W3  = (const float*)d_in[13]; const float* b3  = (const float*)d_in[14];
  const float* g1  = (const float*)d_in[15]; const float* be1 = (const float*)d_in[16];
  const float* g2  = (const float*)d_in[17]; const float* be2 = (const float*)d_in[18];
  float* out = (float*)d_out;

  k_init  <<<1, 64>>>();
  k_prep  <<<M_AT/16, 256>>>(atom_types, atom_xyz, Wt1,bt1, Wt2,bt2, Wt3,bt3);
  k_knn   <<<(N_PTS+127)/128, 256>>>(xyz);
  k_conv1 <<<592, 256>>>(W1, b1);
  k_fin   <<<1, 16>>>(g1, be1, 0);
  k_stage2<<<592, 256>>>(W2, b2);
  k_fin   <<<1, 16>>>(g2, be2, 1);
  k_stage3<<<592, 256>>>(W3, b3, out);
}